// round 12
// baseline (speedup 1.0000x reference)
#include <cuda_runtime.h>

// HybridODENN: B=1024, T=256, H=128, 3 hidden layers, S=6
#define B_DIM 1024
#define T_DIM 256
#define H_DIM 128
#define S_DIM 6
#define ROWS 8                    // array sizing (pad row 7)
#define NROWS 7                   // real rows per CTA
#define GRID 147                  // 146 x 7 + 1 x 2 = 1024
#define NTHREADS 512
#define HSTRIDE 136

// ODE constants
#define C_A_GI 0.01f
#define C_K_I  0.1f
#define C_RHO  0.05f
#define C_EMAX 2.0f
#define C_EC50 5.0f
#define C_VMAX 1.0f
#define C_KM   100.0f
#define C_KL   0.2f

typedef unsigned long long ull;

#define FFMA2(d, a, b) asm("fma.rn.f32x2 %0, %1, %2, %0;" : "+l"(d) : "l"(a), "l"(b))

__device__ __forceinline__ ull add2(ull a, ull b) {
    ull d; asm("add.rn.f32x2 %0, %1, %2;" : "=l"(d) : "l"(a), "l"(b)); return d;
}
__device__ __forceinline__ float2 unpack2(ull v) {
    float lo, hi;
    asm("mov.b64 {%0, %1}, %2;" : "=f"(lo), "=f"(hi) : "l"(v));
    return make_float2(lo, hi);
}
__device__ __forceinline__ ull dup2f(float x) {
    ull d; asm("mov.b64 %0, {%1, %1};" : "=l"(d) : "f"(x)); return d;
}
// fast tanh: 1 - 2/(e^{2x}+1), ~1e-7 rel err
__device__ __forceinline__ float tanh_fast(float x) {
    float e;
    asm("ex2.approx.f32 %0, %1;" : "=f"(e) : "f"(x * 2.8853900817779268f));
    float r;
    asm("rcp.approx.f32 %0, %1;" : "=f"(r) : "f"(e + 1.0f));
    return fmaf(-2.0f, r, 1.0f);
}
// h column swizzle: chunk ck = c>>2 -> ck ^ (ck>>3), keep (c&3)
__device__ __forceinline__ int hswz(int c) {
    int ck = c >> 2;
    int ckp = ck ^ (ck >> 3);
    return ckp * 4 + (c & 3);
}

struct __align__(16) Smem {
    // W_h[l][k][ g'*4 + (c&3) ], g' = (c>>2) ^ ((k>>3)&15)
    float W_h[3][H_DIM][H_DIM];    // 192 KB
    float W_in[9][H_DIM];
    float W_out_p[3][H_DIM][2];    // packed: [opair][k][o&1]
    float b_in[H_DIM];
    float b_h[3][H_DIM];
    float b_out[8];
    float h[2][ROWS * HSTRIDE];    // swizzled cols + padded rows
    float y[ROWS][S_DIM];
    float acc[ROWS][S_DIM];
};

__device__ __forceinline__ float ode_comp(int o, const float* y, float m) {
    float G = y[0], I = y[1], N = y[2], L = y[3], GE = y[4], F = y[5];
    switch (o) {
        case 0: return -C_A_GI * I * G + C_RHO * GE;
        case 1: return __fdividef(C_VMAX * G, C_KM + G)
                       * (1.0f + C_EMAX * __fdividef(L, C_EC50 + L)) - C_K_I * I;
        case 2: return -C_RHO * N;
        case 3: return C_RHO * GE - C_KL * L;
        case 4: return m - C_RHO * GE;
        default: return -C_A_GI * I * F;
    }
}

// fused input layer (FFMA2-packed): warp owns row r; lane -> cols [lane*4, lane*4+4)
__device__ __forceinline__ void input_row(Smem* s, int r, int lane,
                                          float y0, float y1, float y2,
                                          float y3, float y4, float y5,
                                          float ts, float vs)
{
    int jb = lane * 4;
    int so = r * HSTRIDE + ((lane ^ (lane >> 3)) * 4);
    ulonglong2 bb = *reinterpret_cast<const ulonglong2*>(&s->b_in[jb]);
    ull a01 = bb.x, a23 = bb.y;
    float xs[9] = {ts, y0, y1, y2, y3, y4, y5, y3, vs};
    #pragma unroll
    for (int i = 0; i < 9; ++i) {
        ull d = dup2f(xs[i]);
        ulonglong2 q = *reinterpret_cast<const ulonglong2*>(&s->W_in[i][jb]);
        FFMA2(a01, d, q.x);
        FFMA2(a23, d, q.y);
    }
    float2 v01 = unpack2(a01), v23 = unpack2(a23);
    float4 o4;
    o4.x = tanh_fast(v01.x); o4.y = tanh_fast(v01.y);
    o4.z = tanh_fast(v23.x); o4.w = tanh_fast(v23.y);
    *reinterpret_cast<float4*>(&s->h[0][so]) = o4;
}

// R7 x C4 x K8 col-packed FFMA2 mainloop (identical math to r10/r11)
__device__ __forceinline__ void gemm7(const float* hin, int hco0, int hco1,
                                      const ulonglong2 wk0[4], const ulonglong2 wk1[4],
                                      ull acc[8][2])
{
    #pragma unroll
    for (int r = 0; r < NROWS; ++r) {
        float4 ha = *reinterpret_cast<const float4*>(hin + r * HSTRIDE + hco0);
        float4 hb = *reinterpret_cast<const float4*>(hin + r * HSTRIDE + hco1);
        ull d;
        d = dup2f(ha.x); FFMA2(acc[r][0], d, wk0[0].x); FFMA2(acc[r][1], d, wk0[0].y);
        d = dup2f(ha.y); FFMA2(acc[r][0], d, wk0[1].x); FFMA2(acc[r][1], d, wk0[1].y);
        d = dup2f(ha.z); FFMA2(acc[r][0], d, wk0[2].x); FFMA2(acc[r][1], d, wk0[2].y);
        d = dup2f(ha.w); FFMA2(acc[r][0], d, wk0[3].x); FFMA2(acc[r][1], d, wk0[3].y);
        d = dup2f(hb.x); FFMA2(acc[r][0], d, wk1[0].x); FFMA2(acc[r][1], d, wk1[0].y);
        d = dup2f(hb.y); FFMA2(acc[r][0], d, wk1[1].x); FFMA2(acc[r][1], d, wk1[1].y);
        d = dup2f(hb.z); FFMA2(acc[r][0], d, wk1[2].x); FFMA2(acc[r][1], d, wk1[2].y);
        d = dup2f(hb.w); FFMA2(acc[r][0], d, wk1[3].x); FFMA2(acc[r][1], d, wk1[3].y);
    }
}

// 4-round send-select fold over 16-way k-split
__device__ __forceinline__ float2 fold16(ull acc[8][2],
                                         bool b3, bool b2, bool b1, bool b0)
{
    #pragma unroll
    for (int i = 0; i < 4; ++i)
        #pragma unroll
        for (int c = 0; c < 2; ++c) {
            ull snd = b3 ? acc[i][c] : acc[i + 4][c];
            ull rcv = __shfl_xor_sync(0xffffffffu, snd, 8);
            ull kp  = b3 ? acc[i + 4][c] : acc[i][c];
            acc[i][c] = add2(kp, rcv);
        }
    #pragma unroll
    for (int i = 0; i < 2; ++i)
        #pragma unroll
        for (int c = 0; c < 2; ++c) {
            ull snd = b2 ? acc[i][c] : acc[i + 2][c];
            ull rcv = __shfl_xor_sync(0xffffffffu, snd, 4);
            ull kp  = b2 ? acc[i + 2][c] : acc[i][c];
            acc[i][c] = add2(kp, rcv);
        }
    #pragma unroll
    for (int c = 0; c < 2; ++c) {
        ull snd = b1 ? acc[0][c] : acc[1][c];
        ull rcv = __shfl_xor_sync(0xffffffffu, snd, 2);
        ull kp  = b1 ? acc[1][c] : acc[0][c];
        acc[0][c] = add2(kp, rcv);
    }
    ull fin;
    {
        ull snd = b0 ? acc[0][0] : acc[0][1];
        ull rcv = __shfl_xor_sync(0xffffffffu, snd, 1);
        ull kp  = b0 ? acc[0][1] : acc[0][0];
        fin = add2(kp, rcv);
    }
    return unpack2(fin);
}

__global__ void __launch_bounds__(NTHREADS, 1)
hybrid_ode_kernel(const float* __restrict__ init,
                  const float* __restrict__ t_span,
                  const float* __restrict__ meal,
                  const float* __restrict__ tvns,
                  const float* __restrict__ gW_in,
                  const float* __restrict__ gb_in,
                  const float* __restrict__ gW_h,
                  const float* __restrict__ gb_h,
                  const float* __restrict__ gW_out,
                  const float* __restrict__ gb_out,
                  float* __restrict__ out)
{
    extern __shared__ __align__(16) char smem_raw[];
    Smem* s = reinterpret_cast<Smem*>(smem_raw);

    const int tid  = threadIdx.x;
    const int cta  = blockIdx.x;
    const int base = cta * NROWS;
    const int nr   = (B_DIM - base < NROWS) ? (B_DIM - base) : NROWS;

    // ---- one-time weight staging ----
    for (int i = tid; i < 3 * H_DIM * H_DIM; i += NTHREADS) {
        int l = i >> 14;
        int rem = i & 16383;
        int k = rem >> 7, c = rem & 127;
        int gp = (c >> 2) ^ ((k >> 3) & 15);
        s->W_h[l][k][gp * 4 + (c & 3)] = gW_h[i];
    }
    for (int i = tid; i < 9 * H_DIM; i += NTHREADS) (&s->W_in[0][0])[i] = gW_in[i];
    for (int i = tid; i < H_DIM; i += NTHREADS) s->b_in[i] = gb_in[i];
    for (int i = tid; i < 3 * H_DIM; i += NTHREADS) (&s->b_h[0][0])[i] = gb_h[i];
    for (int i = tid; i < H_DIM * S_DIM; i += NTHREADS) {
        int k = i / S_DIM, o = i % S_DIM;
        s->W_out_p[o >> 1][k][o & 1] = gW_out[i];
    }
    if (tid < S_DIM) (&s->b_out[0])[tid] = gb_out[tid];

    // ---- GEMM mapping (identical to r10/r11) ----
    const int w    = tid >> 5;
    const int lane = tid & 31;
    const int ks   = lane & 15;
    const int cg   = lane >> 4;
    const int c0   = w * 8 + cg * 4;
    const int gexp = (((w << 1) + cg) ^ ks) << 2;
    int hco0, hco1;
    {
        int ck0 = 2 * ks, ck1 = 2 * ks + 1;
        hco0 = (ck0 ^ (ck0 >> 3)) * 4;
        hco1 = (ck1 ^ (ck1 >> 3)) * 4;
    }
    const int frow = ((ks >> 3) & 1) * 4 + ((ks >> 2) & 1) * 2 + ((ks >> 1) & 1);
    const int fcol = c0 + 2 * (ks & 1);
    const int fco  = frow * HSTRIDE + hswz(fcol);
    const bool b3 = (ks & 8) != 0, b2 = (ks & 4) != 0, b1 = (ks & 2) != 0, b0 = (ks & 1) != 0;
    const int sw0 = hswz(lane), sw1 = hswz(lane + 32), sw2 = hswz(lane + 64), sw3 = hswz(lane + 96);

    // ---- register-resident ycur (warp w < NROWS owns batch row w) ----
    float yc0 = 0.f, yc1 = 0.f, yc2 = 0.f, yc3 = 0.f, yc4 = 0.f, yc5 = 0.f;
    if (w < NROWS) {
        int rr = (w < nr) ? w : 0;
        const float* ip = init + (size_t)(base + rr) * S_DIM;
        yc0 = ip[0]; yc1 = ip[1]; yc2 = ip[2];
        yc3 = ip[3]; yc4 = ip[4]; yc5 = ip[5];
        if (lane == 0) {
            s->y[w][0] = yc0; s->y[w][1] = yc1; s->y[w][2] = yc2;
            s->y[w][3] = yc3; s->y[w][4] = yc4; s->y[w][5] = yc5;
            s->acc[w][0] = yc0; s->acc[w][1] = yc1; s->acc[w][2] = yc2;
            s->acc[w][3] = yc3; s->acc[w][4] = yc4; s->acc[w][5] = yc5;
            if (w < nr) {
                float* op = out + (size_t)(base + w) * T_DIM * S_DIM;
                op[0] = yc0; op[1] = yc1; op[2] = yc2;
                op[3] = yc3; op[4] = yc4; op[5] = yc5;
            }
        }
    }
    __syncthreads();

    // ---- persistent W registers: k-chunk 0 for layers 0,1 only ----
    ulonglong2 wp0[4], wp1[4];
    #pragma unroll
    for (int i = 0; i < 4; ++i) {
        wp0[i] = *reinterpret_cast<const ulonglong2*>(&s->W_h[0][ks * 8 + i][0] + gexp);
        wp1[i] = *reinterpret_cast<const ulonglong2*>(&s->W_h[1][ks * 8 + i][0] + gexp);
    }

    for (int t = 0; t < T_DIM - 1; ++t) {
        const float T0 = t_span[t], T1 = t_span[t + 1];
        const float dt = T1 - T0;
        const float tm = T0 + 0.5f * dt;
        const float dt6 = dt * (1.0f / 6.0f), dt3 = dt * (1.0f / 3.0f);

        float m0 = 0.f, mm = 0.f, m1 = 0.f, v1 = 0.f, vm = 0.f;
        if (w < NROWS) {
            int rr = (w < nr) ? w : 0;
            size_t ri = (size_t)(base + rr) * T_DIM + t;
            float M0 = meal[ri], M1 = meal[ri + 1];
            float V0 = tvns[ri], V1 = tvns[ri + 1];
            m0 = M0; m1 = M1; mm = 0.5f * (M0 + M1);
            v1 = V1; vm = 0.5f * (V0 + V1);
            input_row(s, w, lane, yc0, yc1, yc2, yc3, yc4, yc5, T0, V0);
        }
        __syncthreads();

        #pragma unroll 1
        for (int st = 0; st < 4; ++st) {
            // ---- L0: h[0] -> h[1] ----
            {
                ulonglong2 wva[4];
                const float* wb = &s->W_h[0][ks * 8][0] + gexp;
                #pragma unroll
                for (int i = 0; i < 4; ++i)
                    wva[i] = *reinterpret_cast<const ulonglong2*>(wb + (4 + i) * H_DIM);
                ull acc[8][2];
                #pragma unroll
                for (int r = 0; r < 8; ++r) { acc[r][0] = 0ull; acc[r][1] = 0ull; }
                gemm7(s->h[0], hco0, hco1, wp0, wva, acc);
                float2 vv = fold16(acc, b3, b2, b1, b0);
                float2 bb = *reinterpret_cast<const float2*>(&s->b_h[0][fcol]);
                float2 rr;
                rr.x = tanh_fast(vv.x + bb.x);
                rr.y = tanh_fast(vv.y + bb.y);
                *reinterpret_cast<float2*>(&s->h[1][fco]) = rr;
                __syncthreads();
            }

            // ---- L1: h[1] -> h[0]; prefetch L2 kc0 during fold ----
            ulonglong2 wvb[4];
            {
                ulonglong2 wva[4];
                const float* wb = &s->W_h[1][ks * 8][0] + gexp;
                #pragma unroll
                for (int i = 0; i < 4; ++i)
                    wva[i] = *reinterpret_cast<const ulonglong2*>(wb + (4 + i) * H_DIM);
                ull acc[8][2];
                #pragma unroll
                for (int r = 0; r < 8; ++r) { acc[r][0] = 0ull; acc[r][1] = 0ull; }
                gemm7(s->h[1], hco0, hco1, wp1, wva, acc);
                // prefetch L2 k-chunk 0 (covers the fold's SHFL latency)
                #pragma unroll
                for (int i = 0; i < 4; ++i)
                    wvb[i] = *reinterpret_cast<const ulonglong2*>(
                        &s->W_h[2][ks * 8 + i][0] + gexp);
                float2 vv = fold16(acc, b3, b2, b1, b0);
                float2 bb = *reinterpret_cast<const float2*>(&s->b_h[1][fcol]);
                float2 rr;
                rr.x = tanh_fast(vv.x + bb.x);
                rr.y = tanh_fast(vv.y + bb.y);
                *reinterpret_cast<float2*>(&s->h[0][fco]) = rr;
                __syncthreads();
            }

            // ---- L2: h[0] -> h[1] ----
            {
                ulonglong2 wva[4];
                const float* wb = &s->W_h[2][ks * 8][0] + gexp;
                #pragma unroll
                for (int i = 0; i < 4; ++i)
                    wva[i] = *reinterpret_cast<const ulonglong2*>(wb + (4 + i) * H_DIM);
                ull acc[8][2];
                #pragma unroll
                for (int r = 0; r < 8; ++r) { acc[r][0] = 0ull; acc[r][1] = 0ull; }
                gemm7(s->h[0], hco0, hco1, wvb, wva, acc);
                float2 vv = fold16(acc, b3, b2, b1, b0);
                float2 bb = *reinterpret_cast<const float2*>(&s->b_h[2][fcol]);
                float2 rr;
                rr.x = tanh_fast(vv.x + bb.x);
                rr.y = tanh_fast(vv.y + bb.y);
                *reinterpret_cast<float2*>(&s->h[1][fco]) = rr;
                __syncthreads();
            }

            // ---- fused epilogue + next-stage input (warps 0..6) ----
            if (w < NROWS) {
                const float* hr = &s->h[1][w * HSTRIDE];
                float hv[4] = {hr[sw0], hr[sw1], hr[sw2], hr[sw3]};
                ull dp0 = 0ull, dp1 = 0ull, dp2 = 0ull;
                #pragma unroll
                for (int q = 0; q < 4; ++q) {
                    ull d = dup2f(hv[q]);
                    int k = lane + 32 * q;
                    FFMA2(dp0, d, *reinterpret_cast<const ull*>(&s->W_out_p[0][k][0]));
                    FFMA2(dp1, d, *reinterpret_cast<const ull*>(&s->W_out_p[1][k][0]));
                    FFMA2(dp2, d, *reinterpret_cast<const ull*>(&s->W_out_p[2][k][0]));
                }
                #pragma unroll
                for (int off = 16; off; off >>= 1) {
                    dp0 = add2(dp0, __shfl_xor_sync(0xffffffffu, dp0, off));
                    dp1 = add2(dp1, __shfl_xor_sync(0xffffffffu, dp1, off));
                    dp2 = add2(dp2, __shfl_xor_sync(0xffffffffu, dp2, off));
                }
                float2 d01 = unpack2(dp0), d23 = unpack2(dp1), d45 = unpack2(dp2);
                float dots[S_DIM] = {d01.x, d01.y, d23.x, d23.y, d45.x, d45.y};

                float msel = (st == 0) ? m0 : ((st == 3) ? m1 : mm);
                float wg   = (st == 0 || st == 3) ? dt6 : dt3;
                float yca[S_DIM] = {yc0, yc1, yc2, yc3, yc4, yc5};
                float nyc[S_DIM];
                if (st < 3) {
                    float cn = (st < 2) ? 0.5f * dt : dt;
                    #pragma unroll
                    for (int o = 0; o < S_DIM; ++o) {
                        float kv = dots[o] + s->b_out[o] + ode_comp(o, yca, msel);
                        float av = s->acc[w][o] + wg * kv;
                        if (lane == 0) s->acc[w][o] = av;
                        nyc[o] = s->y[w][o] + cn * kv;
                    }
                } else {
                    #pragma unroll
                    for (int o = 0; o < S_DIM; ++o) {
                        float kv = dots[o] + s->b_out[o] + ode_comp(o, yca, msel);
                        float av = s->acc[w][o] + wg * kv;
                        nyc[o] = av;
                        if (lane == 0) {
                            s->acc[w][o] = av;
                            s->y[w][o] = av;
                            if (w < nr)
                                out[(size_t)(base + w) * T_DIM * S_DIM
                                    + (size_t)(t + 1) * S_DIM + o] = av;
                        }
                    }
                }
                yc0 = nyc[0]; yc1 = nyc[1]; yc2 = nyc[2];
                yc3 = nyc[3]; yc4 = nyc[4]; yc5 = nyc[5];
                if (st < 3) {
                    float ts_n = (st == 2) ? T1 : tm;
                    float vs_n = (st == 2) ? v1 : vm;
                    input_row(s, w, lane, yc0, yc1, yc2, yc3, yc4, yc5, ts_n, vs_n);
                }
            }
            __syncthreads();
        } // stages
    } // steps
}

extern "C" void kernel_launch(void* const* d_in, const int* in_sizes, int n_in,
                              void* d_out, int out_size) {
    const float* init   = (const float*)d_in[0];
    const float* t_span = (const float*)d_in[1];
    const float* meal   = (const float*)d_in[2];
    const float* tvns   = (const float*)d_in[3];
    const float* W_in   = (const float*)d_in[4];
    const float* b_in   = (const float*)d_in[5];
    const float* W_h    = (const float*)d_in[6];
    const float* b_h    = (const float*)d_in[7];
    const float* W_out  = (const float*)d_in[8];
    const float* b_out  = (const float*)d_in[9];
    float* out = (float*)d_out;

    const size_t smem_bytes = sizeof(Smem);  // ~206 KB
    cudaFuncSetAttribute(hybrid_ode_kernel,
                         cudaFuncAttributeMaxDynamicSharedMemorySize,
                         (int)smem_bytes);

    hybrid_ode_kernel<<<GRID, NTHREADS, smem_bytes>>>(
        init, t_span, meal, tvns, W_in, b_in, W_h, b_h, W_out, b_out, out);
}

// round 13
// speedup vs baseline: 1.0086x; 1.0086x over previous
#include <cuda_runtime.h>

// HybridODENN: B=1024, T=256, H=128, 3 hidden layers, S=6
#define B_DIM 1024
#define T_DIM 256
#define H_DIM 128
#define S_DIM 6
#define ROWS 8                    // array sizing (pad row 7)
#define NROWS 7                   // real rows per CTA
#define GRID 147                  // 146 x 7 + 1 x 2 = 1024
#define NTHREADS 512
#define HSTRIDE 136

// ODE constants
#define C_A_GI 0.01f
#define C_K_I  0.1f
#define C_RHO  0.05f
#define C_EMAX 2.0f
#define C_EC50 5.0f
#define C_VMAX 1.0f
#define C_KM   100.0f
#define C_KL   0.2f

typedef unsigned long long ull;

#define FFMA2(d, a, b) asm("fma.rn.f32x2 %0, %1, %2, %0;" : "+l"(d) : "l"(a), "l"(b))

__device__ __forceinline__ ull add2(ull a, ull b) {
    ull d; asm("add.rn.f32x2 %0, %1, %2;" : "=l"(d) : "l"(a), "l"(b)); return d;
}
__device__ __forceinline__ float2 unpack2(ull v) {
    float lo, hi;
    asm("mov.b64 {%0, %1}, %2;" : "=f"(lo), "=f"(hi) : "l"(v));
    return make_float2(lo, hi);
}
__device__ __forceinline__ ull dup2f(float x) {
    ull d; asm("mov.b64 %0, {%1, %1};" : "=l"(d) : "f"(x)); return d;
}
// fast tanh: 1 - 2/(e^{2x}+1), ~1e-7 rel err
__device__ __forceinline__ float tanh_fast(float x) {
    float e;
    asm("ex2.approx.f32 %0, %1;" : "=f"(e) : "f"(x * 2.8853900817779268f));
    float r;
    asm("rcp.approx.f32 %0, %1;" : "=f"(r) : "f"(e + 1.0f));
    return fmaf(-2.0f, r, 1.0f);
}
// h column swizzle: chunk ck = c>>2 -> ck ^ (ck>>3), keep (c&3)
__device__ __forceinline__ int hswz(int c) {
    int ck = c >> 2;
    int ckp = ck ^ (ck >> 3);
    return ckp * 4 + (c & 3);
}

struct __align__(16) Smem {
    // W_h[l][k][ g'*4 + (c&3) ], g' = (c>>2) ^ ((k>>3)&15)
    float W_h[3][H_DIM][H_DIM];    // 192 KB
    float W_in[9][H_DIM];
    float W_out_p[3][H_DIM][2];    // packed: [opair][k][o&1]
    float b_in[H_DIM];
    float b_h[3][H_DIM];
    float b_out[8];
    float h[2][ROWS * HSTRIDE];    // swizzled cols + padded rows
    float y[ROWS][S_DIM];
    float acc[ROWS][S_DIM];
};

__device__ __forceinline__ float ode_comp(int o, const float* y, float m) {
    float G = y[0], I = y[1], N = y[2], L = y[3], GE = y[4], F = y[5];
    switch (o) {
        case 0: return -C_A_GI * I * G + C_RHO * GE;
        case 1: return __fdividef(C_VMAX * G, C_KM + G)
                       * (1.0f + C_EMAX * __fdividef(L, C_EC50 + L)) - C_K_I * I;
        case 2: return -C_RHO * N;
        case 3: return C_RHO * GE - C_KL * L;
        case 4: return m - C_RHO * GE;
        default: return -C_A_GI * I * F;
    }
}

// fused input layer (FFMA2-packed): warp owns row r; lane -> cols [lane*4, lane*4+4)
__device__ __forceinline__ void input_row(Smem* s, int r, int lane,
                                          float y0, float y1, float y2,
                                          float y3, float y4, float y5,
                                          float ts, float vs)
{
    int jb = lane * 4;
    int so = r * HSTRIDE + ((lane ^ (lane >> 3)) * 4);
    ulonglong2 bb = *reinterpret_cast<const ulonglong2*>(&s->b_in[jb]);
    ull a01 = bb.x, a23 = bb.y;
    float xs[9] = {ts, y0, y1, y2, y3, y4, y5, y3, vs};
    #pragma unroll
    for (int i = 0; i < 9; ++i) {
        ull d = dup2f(xs[i]);
        ulonglong2 q = *reinterpret_cast<const ulonglong2*>(&s->W_in[i][jb]);
        FFMA2(a01, d, q.x);
        FFMA2(a23, d, q.y);
    }
    float2 v01 = unpack2(a01), v23 = unpack2(a23);
    float4 o4;
    o4.x = tanh_fast(v01.x); o4.y = tanh_fast(v01.y);
    o4.z = tanh_fast(v23.x); o4.w = tanh_fast(v23.y);
    *reinterpret_cast<float4*>(&s->h[0][so]) = o4;
}

__global__ void __launch_bounds__(NTHREADS, 1)
hybrid_ode_kernel(const float* __restrict__ init,
                  const float* __restrict__ t_span,
                  const float* __restrict__ meal,
                  const float* __restrict__ tvns,
                  const float* __restrict__ gW_in,
                  const float* __restrict__ gb_in,
                  const float* __restrict__ gW_h,
                  const float* __restrict__ gb_h,
                  const float* __restrict__ gW_out,
                  const float* __restrict__ gb_out,
                  float* __restrict__ out)
{
    extern __shared__ __align__(16) char smem_raw[];
    Smem* s = reinterpret_cast<Smem*>(smem_raw);

    const int tid  = threadIdx.x;
    const int cta  = blockIdx.x;
    const int base = cta * NROWS;
    const int nr   = (B_DIM - base < NROWS) ? (B_DIM - base) : NROWS;

    // ---- one-time weight staging ----
    for (int i = tid; i < 3 * H_DIM * H_DIM; i += NTHREADS) {
        int l = i >> 14;
        int rem = i & 16383;
        int k = rem >> 7, c = rem & 127;
        int gp = (c >> 2) ^ ((k >> 3) & 15);
        s->W_h[l][k][gp * 4 + (c & 3)] = gW_h[i];
    }
    for (int i = tid; i < 9 * H_DIM; i += NTHREADS) (&s->W_in[0][0])[i] = gW_in[i];
    for (int i = tid; i < H_DIM; i += NTHREADS) s->b_in[i] = gb_in[i];
    for (int i = tid; i < 3 * H_DIM; i += NTHREADS) (&s->b_h[0][0])[i] = gb_h[i];
    for (int i = tid; i < H_DIM * S_DIM; i += NTHREADS) {
        int k = i / S_DIM, o = i % S_DIM;
        s->W_out_p[o >> 1][k][o & 1] = gW_out[i];
    }
    if (tid < S_DIM) (&s->b_out[0])[tid] = gb_out[tid];

    // ---- GEMM mapping (identical to r10/r11) ----
    const int w    = tid >> 5;
    const int lane = tid & 31;
    const int ks   = lane & 15;
    const int cg   = lane >> 4;
    const int c0   = w * 8 + cg * 4;
    const int gexp = (((w << 1) + cg) ^ ks) << 2;
    int hco0, hco1;
    {
        int ck0 = 2 * ks, ck1 = 2 * ks + 1;
        hco0 = (ck0 ^ (ck0 >> 3)) * 4;
        hco1 = (ck1 ^ (ck1 >> 3)) * 4;
    }
    const int frow = ((ks >> 3) & 1) * 4 + ((ks >> 2) & 1) * 2 + ((ks >> 1) & 1);
    const int fcol = c0 + 2 * (ks & 1);
    const int fco  = frow * HSTRIDE + hswz(fcol);
    const bool b3 = (ks & 8) != 0, b2 = (ks & 4) != 0, b1 = (ks & 2) != 0, b0 = (ks & 1) != 0;
    const int sw0 = hswz(lane), sw1 = hswz(lane + 32), sw2 = hswz(lane + 64), sw3 = hswz(lane + 96);

    // ---- register-resident ycur (warp w < NROWS owns batch row w) ----
    float yc0 = 0.f, yc1 = 0.f, yc2 = 0.f, yc3 = 0.f, yc4 = 0.f, yc5 = 0.f;
    if (w < NROWS) {
        int rr = (w < nr) ? w : 0;
        const float* ip = init + (size_t)(base + rr) * S_DIM;
        yc0 = ip[0]; yc1 = ip[1]; yc2 = ip[2];
        yc3 = ip[3]; yc4 = ip[4]; yc5 = ip[5];
        if (lane == 0) {
            s->y[w][0] = yc0; s->y[w][1] = yc1; s->y[w][2] = yc2;
            s->y[w][3] = yc3; s->y[w][4] = yc4; s->y[w][5] = yc5;
            s->acc[w][0] = yc0; s->acc[w][1] = yc1; s->acc[w][2] = yc2;
            s->acc[w][3] = yc3; s->acc[w][4] = yc4; s->acc[w][5] = yc5;
            if (w < nr) {
                float* op = out + (size_t)(base + w) * T_DIM * S_DIM;
                *reinterpret_cast<float2*>(op)     = make_float2(yc0, yc1);
                *reinterpret_cast<float2*>(op + 2) = make_float2(yc2, yc3);
                *reinterpret_cast<float2*>(op + 4) = make_float2(yc4, yc5);
            }
        }
    }
    __syncthreads();

    // ---- persistent W registers: k-chunk 0, all 3 layers (r11-proven) ----
    ulonglong2 wp0[4], wp1[4], wp2[4];
    #pragma unroll
    for (int i = 0; i < 4; ++i) {
        wp0[i] = *reinterpret_cast<const ulonglong2*>(&s->W_h[0][ks * 8 + i][0] + gexp);
        wp1[i] = *reinterpret_cast<const ulonglong2*>(&s->W_h[1][ks * 8 + i][0] + gexp);
        wp2[i] = *reinterpret_cast<const ulonglong2*>(&s->W_h[2][ks * 8 + i][0] + gexp);
    }

    for (int t = 0; t < T_DIM - 1; ++t) {
        const float T0 = t_span[t], T1 = t_span[t + 1];
        const float dt = T1 - T0;
        const float tm = T0 + 0.5f * dt;
        const float dt6 = dt * (1.0f / 6.0f), dt3 = dt * (1.0f / 3.0f);

        float m0 = 0.f, mm = 0.f, m1 = 0.f, v1 = 0.f, vm = 0.f;
        if (w < NROWS) {
            int rr = (w < nr) ? w : 0;
            size_t ri = (size_t)(base + rr) * T_DIM + t;
            float M0 = meal[ri], M1 = meal[ri + 1];
            float V0 = tvns[ri], V1 = tvns[ri + 1];
            m0 = M0; m1 = M1; mm = 0.5f * (M0 + M1);
            v1 = V1; vm = 0.5f * (V0 + V1);
            input_row(s, w, lane, yc0, yc1, yc2, yc3, yc4, yc5, T0, V0);
        }
        __syncthreads();

        #pragma unroll 1
        for (int st = 0; st < 4; ++st) {
            // ---- 3 hidden layers (r11 GEMM: per-layer wva load, wp persistent) ----
            #pragma unroll
            for (int L = 0; L < 3; ++L) {
                const float* hin  = s->h[L & 1];
                float*       hout = s->h[(L & 1) ^ 1];
                const float* wbase = &s->W_h[L][ks * 8][0] + gexp;

                ulonglong2 wv[4];
                #pragma unroll
                for (int i = 0; i < 4; ++i)
                    wv[i] = *reinterpret_cast<const ulonglong2*>(wbase + (4 + i) * H_DIM);

                ull acc[8][2];
                #pragma unroll
                for (int r = 0; r < 8; ++r) { acc[r][0] = 0ull; acc[r][1] = 0ull; }

                #pragma unroll
                for (int r = 0; r < NROWS; ++r) {
                    float4 ha = *reinterpret_cast<const float4*>(hin + r * HSTRIDE + hco0);
                    float4 hb = *reinterpret_cast<const float4*>(hin + r * HSTRIDE + hco1);
                    ull d;
                    if (L == 0) {
                        d = dup2f(ha.x); FFMA2(acc[r][0], d, wp0[0].x); FFMA2(acc[r][1], d, wp0[0].y);
                        d = dup2f(ha.y); FFMA2(acc[r][0], d, wp0[1].x); FFMA2(acc[r][1], d, wp0[1].y);
                        d = dup2f(ha.z); FFMA2(acc[r][0], d, wp0[2].x); FFMA2(acc[r][1], d, wp0[2].y);
                        d = dup2f(ha.w); FFMA2(acc[r][0], d, wp0[3].x); FFMA2(acc[r][1], d, wp0[3].y);
                    } else if (L == 1) {
                        d = dup2f(ha.x); FFMA2(acc[r][0], d, wp1[0].x); FFMA2(acc[r][1], d, wp1[0].y);
                        d = dup2f(ha.y); FFMA2(acc[r][0], d, wp1[1].x); FFMA2(acc[r][1], d, wp1[1].y);
                        d = dup2f(ha.z); FFMA2(acc[r][0], d, wp1[2].x); FFMA2(acc[r][1], d, wp1[2].y);
                        d = dup2f(ha.w); FFMA2(acc[r][0], d, wp1[3].x); FFMA2(acc[r][1], d, wp1[3].y);
                    } else {
                        d = dup2f(ha.x); FFMA2(acc[r][0], d, wp2[0].x); FFMA2(acc[r][1], d, wp2[0].y);
                        d = dup2f(ha.y); FFMA2(acc[r][0], d, wp2[1].x); FFMA2(acc[r][1], d, wp2[1].y);
                        d = dup2f(ha.z); FFMA2(acc[r][0], d, wp2[2].x); FFMA2(acc[r][1], d, wp2[2].y);
                        d = dup2f(ha.w); FFMA2(acc[r][0], d, wp2[3].x); FFMA2(acc[r][1], d, wp2[3].y);
                    }
                    d = dup2f(hb.x); FFMA2(acc[r][0], d, wv[0].x); FFMA2(acc[r][1], d, wv[0].y);
                    d = dup2f(hb.y); FFMA2(acc[r][0], d, wv[1].x); FFMA2(acc[r][1], d, wv[1].y);
                    d = dup2f(hb.z); FFMA2(acc[r][0], d, wv[2].x); FFMA2(acc[r][1], d, wv[2].y);
                    d = dup2f(hb.w); FFMA2(acc[r][0], d, wv[3].x); FFMA2(acc[r][1], d, wv[3].y);
                }

                // ---- 4-round send-select fold over 16-way k-split ----
                #pragma unroll
                for (int i = 0; i < 4; ++i)
                    #pragma unroll
                    for (int c = 0; c < 2; ++c) {
                        ull snd = b3 ? acc[i][c] : acc[i + 4][c];
                        ull rcv = __shfl_xor_sync(0xffffffffu, snd, 8);
                        ull kp  = b3 ? acc[i + 4][c] : acc[i][c];
                        acc[i][c] = add2(kp, rcv);
                    }
                #pragma unroll
                for (int i = 0; i < 2; ++i)
                    #pragma unroll
                    for (int c = 0; c < 2; ++c) {
                        ull snd = b2 ? acc[i][c] : acc[i + 2][c];
                        ull rcv = __shfl_xor_sync(0xffffffffu, snd, 4);
                        ull kp  = b2 ? acc[i + 2][c] : acc[i][c];
                        acc[i][c] = add2(kp, rcv);
                    }
                #pragma unroll
                for (int c = 0; c < 2; ++c) {
                    ull snd = b1 ? acc[0][c] : acc[1][c];
                    ull rcv = __shfl_xor_sync(0xffffffffu, snd, 2);
                    ull kp  = b1 ? acc[1][c] : acc[0][c];
                    acc[0][c] = add2(kp, rcv);
                }
                ull fin;
                {
                    ull snd = b0 ? acc[0][0] : acc[0][1];
                    ull rcv = __shfl_xor_sync(0xffffffffu, snd, 1);
                    ull kp  = b0 ? acc[0][1] : acc[0][0];
                    fin = add2(kp, rcv);
                }

                float2 vv = unpack2(fin);
                float2 bb = *reinterpret_cast<const float2*>(&s->b_h[L][fcol]);
                float2 rr;
                rr.x = tanh_fast(vv.x + bb.x);
                rr.y = tanh_fast(vv.y + bb.y);
                *reinterpret_cast<float2*>(&hout[fco]) = rr;
                __syncthreads();
            }

            // ---- fused epilogue (FFMA2-packed W_out) + next-stage input ----
            if (w < NROWS) {
                const float* hr = &s->h[1][w * HSTRIDE];
                float hv[4] = {hr[sw0], hr[sw1], hr[sw2], hr[sw3]};
                ull dp0 = 0ull, dp1 = 0ull, dp2 = 0ull;
                #pragma unroll
                for (int q = 0; q < 4; ++q) {
                    ull d = dup2f(hv[q]);
                    int k = lane + 32 * q;
                    FFMA2(dp0, d, *reinterpret_cast<const ull*>(&s->W_out_p[0][k][0]));
                    FFMA2(dp1, d, *reinterpret_cast<const ull*>(&s->W_out_p[1][k][0]));
                    FFMA2(dp2, d, *reinterpret_cast<const ull*>(&s->W_out_p[2][k][0]));
                }
                #pragma unroll
                for (int off = 16; off; off >>= 1) {
                    dp0 = add2(dp0, __shfl_xor_sync(0xffffffffu, dp0, off));
                    dp1 = add2(dp1, __shfl_xor_sync(0xffffffffu, dp1, off));
                    dp2 = add2(dp2, __shfl_xor_sync(0xffffffffu, dp2, off));
                }
                float2 d01 = unpack2(dp0), d23 = unpack2(dp1), d45 = unpack2(dp2);
                float dots[S_DIM] = {d01.x, d01.y, d23.x, d23.y, d45.x, d45.y};

                float msel = (st == 0) ? m0 : ((st == 3) ? m1 : mm);
                float wg   = (st == 0 || st == 3) ? dt6 : dt3;
                float yca[S_DIM] = {yc0, yc1, yc2, yc3, yc4, yc5};
                float nyc[S_DIM];
                if (st < 3) {
                    float cn = (st < 2) ? 0.5f * dt : dt;
                    #pragma unroll
                    for (int o = 0; o < S_DIM; ++o) {
                        float kv = dots[o] + s->b_out[o] + ode_comp(o, yca, msel);
                        float av = s->acc[w][o] + wg * kv;
                        if (lane == 0) s->acc[w][o] = av;
                        nyc[o] = s->y[w][o] + cn * kv;
                    }
                } else {
                    #pragma unroll
                    for (int o = 0; o < S_DIM; ++o) {
                        float kv = dots[o] + s->b_out[o] + ode_comp(o, yca, msel);
                        float av = s->acc[w][o] + wg * kv;
                        nyc[o] = av;
                        if (lane == 0) {
                            s->acc[w][o] = av;
                            s->y[w][o] = av;
                        }
                    }
                    if (lane == 0 && w < nr) {
                        float* op = out + (size_t)(base + w) * T_DIM * S_DIM
                                        + (size_t)(t + 1) * S_DIM;
                        *reinterpret_cast<float2*>(op)     = make_float2(nyc[0], nyc[1]);
                        *reinterpret_cast<float2*>(op + 2) = make_float2(nyc[2], nyc[3]);
                        *reinterpret_cast<float2*>(op + 4) = make_float2(nyc[4], nyc[5]);
                    }
                }
                yc0 = nyc[0]; yc1 = nyc[1]; yc2 = nyc[2];
                yc3 = nyc[3]; yc4 = nyc[4]; yc5 = nyc[5];
                if (st < 3) {
                    float ts_n = (st == 2) ? T1 : tm;
                    float vs_n = (st == 2) ? v1 : vm;
                    input_row(s, w, lane, yc0, yc1, yc2, yc3, yc4, yc5, ts_n, vs_n);
                }
            }
            __syncthreads();
        } // stages
    } // steps
}

extern "C" void kernel_launch(void* const* d_in, const int* in_sizes, int n_in,
                              void* d_out, int out_size) {
    const float* init   = (const float*)d_in[0];
    const float* t_span = (const float*)d_in[1];
    const float* meal   = (const float*)d_in[2];
    const float* tvns   = (const float*)d_in[3];
    const float* W_in   = (const float*)d_in[4];
    const float* b_in   = (const float*)d_in[5];
    const float* W_h    = (const float*)d_in[6];
    const float* b_h    = (const float*)d_in[7];
    const float* W_out  = (const float*)d_in[8];
    const float* b_out  = (const float*)d_in[9];
    float* out = (float*)d_out;

    const size_t smem_bytes = sizeof(Smem);  // ~206 KB
    cudaFuncSetAttribute(hybrid_ode_kernel,
                         cudaFuncAttributeMaxDynamicSharedMemorySize,
                         (int)smem_bytes);

    hybrid_ode_kernel<<<GRID, NTHREADS, smem_bytes>>>(
        init, t_span, meal, tvns, W_in, b_in, W_h, b_h, W_out, b_out, out);
}